// round 6
// baseline (speedup 1.0000x reference)
#include <cuda_runtime.h>
#include <cstdint>
#include <math.h>

#define BATCH    4
#define SEQLEN   4096
#define DIM      1024
#define HEADS    16
#define HEAD_DIM 64
#define SEG      64
#define NSEG     (SEQLEN / SEG)     // 64
#define KSEG     (SEG / 2)          // 32 (dilation 2)
#define KDIM     1024               // GEMM reduction dim
#define SCALE    0.125f             // 64^-0.5

// ---------------- scratch (static device globals; no allocs allowed) --------
__device__ float g_Xc[BATCH * SEQLEN * DIM];               // tf32-rounded x
__device__ float g_Q [BATCH * SEQLEN * DIM];               // hilbert-ordered Q
__device__ float g_KV[BATCH * (SEQLEN / 2) * (2 * DIM)];   // dilated K|V
__device__ float g_O [BATCH * SEQLEN * DIM];               // attn out (tf32-rounded)
__device__ float g_WqkvT[3 * DIM * DIM];                   // w_qkv^T, tf32-rounded
__device__ float g_WprojT[DIM * DIM];                      // w_proj^T, tf32-rounded
__device__ int   g_qrow [BATCH * SEQLEN];
__device__ int   g_kvrow[BATCH * (SEQLEN / 2)];

// ---------------- helpers -----------------------------------------------------
__device__ __forceinline__ uint32_t smem_u32(const void* p) {
    uint32_t a;
    asm("{ .reg .u64 t; cvta.to.shared.u64 t, %1; cvt.u32.u64 %0, t; }" : "=r"(a) : "l"(p));
    return a;
}
__device__ __forceinline__ float tf32r(float v) {
    uint32_t u;
    asm("cvt.rna.tf32.f32 %0, %1;" : "=r"(u) : "f"(v));
    return __uint_as_float(u);
}
__device__ __forceinline__ float4 tf32x4(float4 v) {
    v.x = tf32r(v.x); v.y = tf32r(v.y); v.z = tf32r(v.z); v.w = tf32r(v.w);
    return v;
}
__device__ __forceinline__ void cp_async16(uint32_t dst, const void* src) {
    asm volatile("cp.async.ca.shared.global [%0], [%1], 16;" :: "r"(dst), "l"(src));
}
__device__ __forceinline__ void cp_commit() {
    asm volatile("cp.async.commit_group;" ::: "memory");
}
template <int N>
__device__ __forceinline__ void cp_wait() {
    asm volatile("cp.async.wait_group %0;" :: "n"(N) : "memory");
}

// ---------------- build gather tables ---------------------------------------
__global__ void build_maps_kernel(const int* __restrict__ hmap) {
    int t = blockIdx.x * blockDim.x + threadIdx.x;
    if (t < BATCH * SEQLEN) {
        int b = t / SEQLEN, i = t % SEQLEN;
        g_qrow[t] = b * SEQLEN + hmap[i];
    }
    if (t < BATCH * (SEQLEN / 2)) {
        int b = t / (SEQLEN / 2), m = t % (SEQLEN / 2);
        int s = m / KSEG, j = m % KSEG;
        g_kvrow[t] = b * SEQLEN + hmap[s * SEG + 2 * j];
    }
}

// ---------------- convert x to tf32-rounded copy -----------------------------
__global__ void convert_x_kernel(const float* __restrict__ x) {
    long t = (long)blockIdx.x * blockDim.x + threadIdx.x;
    float4 v = ((const float4*)x)[t];
    ((float4*)g_Xc)[t] = tf32x4(v);
}

// ---------------- weight transpose + tf32 round ------------------------------
__global__ void transpose_kernel(const float* __restrict__ W, float* __restrict__ Wt,
                                 int rows, int cols) {  // W[rows][cols] -> Wt[cols][rows]
    __shared__ float t[32][33];
    int bx = blockIdx.x * 32, by = blockIdx.y * 32;
#pragma unroll
    for (int i = 0; i < 32; i += 8) {
        int y = by + threadIdx.y + i, x = bx + threadIdx.x;
        t[threadIdx.y + i][threadIdx.x] = W[(long)y * cols + x];
    }
    __syncthreads();
#pragma unroll
    for (int i = 0; i < 32; i += 8) {
        int y = bx + threadIdx.y + i, x = by + threadIdx.x;
        Wt[(long)y * rows + x] = tf32r(t[threadIdx.x][threadIdx.y + i]);
    }
}

// ---------------- tf32 mma.sync GEMM -----------------------------------------
// C[M,N] = A[rowid[m], :] @ Bt[n, :]^T.
// CTA tile 256x128, 8 warps in 4(M)x2(N), warp tile 64x64.
// K-chunk 32, 4-stage cp.async ring, ks-level fragment double-buffer.
#define PAD        36
#define A_ROWS     256
#define B_ROWS     128
#define STAGE_F_A  (A_ROWS * PAD)             // 9216 floats
#define STAGE_F_B  (B_ROWS * PAD)             // 4608 floats
#define STAGE_BYTES ((STAGE_F_A + STAGE_F_B) * 4)   // 55296
#define NSTAGE     4
#define GSMEM      (NSTAGE * STAGE_BYTES)     // 221184
#define NCHUNK     (KDIM / 32)                // 32

extern __shared__ __align__(16) char dynsmem[];

__global__ __launch_bounds__(256, 1)
void gemm_mma_kernel(const float* __restrict__ A, const float* __restrict__ Bt,
                     float* __restrict__ C, const int* __restrict__ rowidx, int ldc)
{
    __shared__ int rowid[A_ROWS];

    const int tid   = threadIdx.x;
    const int wid   = tid >> 5;       // 0..7
    const int lane  = tid & 31;
    const int gid   = lane >> 2;      // 0..7
    const int tidg  = lane & 3;       // 0..3
    const int warp_m = wid >> 1;      // 0..3
    const int warp_n = wid & 1;       // 0..1
    const int bm = blockIdx.y * A_ROWS;
    const int bn = blockIdx.x * B_ROWS;

    rowid[tid] = rowidx ? rowidx[bm + tid] : (bm + tid);
    __syncthreads();

    const uint32_t smb = smem_u32(dynsmem);

    auto issue = [&](int chunk) {
        const int s = chunk & (NSTAGE - 1);
        const int koff = chunk * 32;
        const uint32_t sA = smb + s * STAGE_BYTES;
        const uint32_t sB = sA + STAGE_F_A * 4;
#pragma unroll
        for (int i = 0; i < 8; i++) {                 // A: 256 rows x 8 granules
            int idx = tid + i * 256;
            int row = idx >> 3, c = idx & 7;
            cp_async16(sA + (row * PAD + c * 4) * 4,
                       A + (long)rowid[row] * KDIM + koff + c * 4);
        }
#pragma unroll
        for (int i = 0; i < 4; i++) {                 // B: 128 rows x 8 granules
            int idx = tid + i * 256;
            int row = idx >> 3, c = idx & 7;
            cp_async16(sB + (row * PAD + c * 4) * 4,
                       Bt + (long)(bn + row) * KDIM + koff + c * 4);
        }
        cp_commit();
    };

    float acc[4][8][4];
#pragma unroll
    for (int i = 0; i < 4; i++)
#pragma unroll
        for (int j = 0; j < 8; j++)
#pragma unroll
            for (int r = 0; r < 4; r++) acc[i][j][r] = 0.0f;

    issue(0); issue(1); issue(2);

    uint32_t af[2][4][4], bf[2][8][2];

    auto load_frags = [&](const uint32_t* As, const uint32_t* Bs, int ks, int buf) {
        const int k0 = ks * 8;
#pragma unroll
        for (int mt = 0; mt < 4; ++mt) {
            int r = warp_m * 64 + mt * 16 + gid;
            af[buf][mt][0] = As[r * PAD + k0 + tidg];
            af[buf][mt][1] = As[(r + 8) * PAD + k0 + tidg];
            af[buf][mt][2] = As[r * PAD + k0 + tidg + 4];
            af[buf][mt][3] = As[(r + 8) * PAD + k0 + tidg + 4];
        }
#pragma unroll
        for (int nt = 0; nt < 8; ++nt) {
            int rn = warp_n * 64 + nt * 8 + gid;
            bf[buf][nt][0] = Bs[rn * PAD + k0 + tidg];
            bf[buf][nt][1] = Bs[rn * PAD + k0 + tidg + 4];
        }
    };

    for (int c = 0; c < NCHUNK; ++c) {
        __syncthreads();                       // stage (c+3)%4 free of readers
        if (c + 3 < NCHUNK) issue(c + 3);
        else                cp_commit();       // empty group keeps wait<3> exact
        cp_wait<3>();                          // chunk c resident
        __syncthreads();

        const uint32_t* As = (const uint32_t*)(dynsmem + (c & (NSTAGE - 1)) * STAGE_BYTES);
        const uint32_t* Bs = As + STAGE_F_A;

        load_frags(As, Bs, 0, 0);
#pragma unroll
        for (int ks = 0; ks < 4; ++ks) {
            const int cur = ks & 1;
            if (ks < 3) load_frags(As, Bs, ks + 1, cur ^ 1);
#pragma unroll
            for (int mt = 0; mt < 4; ++mt)
#pragma unroll
                for (int nt = 0; nt < 8; ++nt) {
                    asm volatile(
                        "mma.sync.aligned.m16n8k8.row.col.f32.tf32.tf32.f32 "
                        "{%0,%1,%2,%3}, {%4,%5,%6,%7}, {%8,%9}, {%0,%1,%2,%3};"
                        : "+f"(acc[mt][nt][0]), "+f"(acc[mt][nt][1]),
                          "+f"(acc[mt][nt][2]), "+f"(acc[mt][nt][3])
                        : "r"(af[cur][mt][0]), "r"(af[cur][mt][1]),
                          "r"(af[cur][mt][2]), "r"(af[cur][mt][3]),
                          "r"(bf[cur][nt][0]), "r"(bf[cur][nt][1]));
                }
        }
    }

    // ---- epilogue ----
#pragma unroll
    for (int mt = 0; mt < 4; ++mt) {
        const int row0 = bm + warp_m * 64 + mt * 16 + gid;
#pragma unroll
        for (int nt = 0; nt < 8; ++nt) {
            const int col = bn + warp_n * 64 + nt * 8 + tidg * 2;
            float2 v0 = {acc[mt][nt][0], acc[mt][nt][1]};
            float2 v1 = {acc[mt][nt][2], acc[mt][nt][3]};
            *(float2*)(C + (long)row0 * ldc + col)       = v0;
            *(float2*)(C + (long)(row0 + 8) * ldc + col) = v1;
        }
    }
}

// ---------------- fused segment attention (fp32, vectorized smem) ------------
__global__ __launch_bounds__(256)
void attn_kernel(const int* __restrict__ hmap)
{
    const int s = blockIdx.x, h = blockIdx.y, b = blockIdx.z;
    __shared__ float Qs[64][68];
    __shared__ float Ks[32][68];
    __shared__ float Vs[32][68];
    __shared__ float Ss[64][33];

    const int tid = threadIdx.x;

    const float* Qbase = g_Q + ((long)(b * SEQLEN + s * SEG)) * DIM + h * HEAD_DIM;
    for (int l = tid; l < 64 * 16; l += 256) {
        int r = l >> 4, g = l & 15;
        *(float4*)&Qs[r][g * 4] = *(const float4*)(Qbase + (long)r * DIM + g * 4);
    }
    const float* Kbase = g_KV + ((long)(b * (SEQLEN / 2) + s * KSEG)) * (2 * DIM) + h * HEAD_DIM;
    const float* Vbase = Kbase + DIM;
    for (int l = tid; l < 32 * 16; l += 256) {
        int r = l >> 4, g = l & 15;
        int gp = g ^ ((r >> 3) & 3);                       // K swizzle
        *(float4*)&Ks[r][gp * 4] = *(const float4*)(Kbase + (long)r * (2 * DIM) + g * 4);
        *(float4*)&Vs[r][g * 4]  = *(const float4*)(Vbase + (long)r * (2 * DIM) + g * 4);
    }
    __syncthreads();

    const int r  = tid >> 2;
    const int cg = (tid & 3) * 8;
    {
        float acc[8] = {0, 0, 0, 0, 0, 0, 0, 0};
#pragma unroll
        for (int gd = 0; gd < 16; ++gd) {
            float4 q = *(const float4*)&Qs[r][gd * 4];
#pragma unroll
            for (int cc = 0; cc < 8; ++cc) {
                const int row = cg + cc;
                float4 kv = *(const float4*)&Ks[row][(gd ^ ((row >> 3) & 3)) * 4];
                acc[cc] += q.x * kv.x + q.y * kv.y + q.z * kv.z + q.w * kv.w;
            }
        }
#pragma unroll
        for (int cc = 0; cc < 8; ++cc) Ss[r][cg + cc] = acc[cc] * SCALE;
    }
    __syncthreads();

    if (tid < 64) {
        float mx = -1e30f;
#pragma unroll
        for (int j = 0; j < 32; j++) mx = fmaxf(mx, Ss[tid][j]);
        float sum = 0.0f;
#pragma unroll
        for (int j = 0; j < 32; j++) {
            float e = __expf(Ss[tid][j] - mx);
            Ss[tid][j] = e;
            sum += e;
        }
        float inv = 1.0f / sum;
#pragma unroll
        for (int j = 0; j < 32; j++) Ss[tid][j] *= inv;
    }
    __syncthreads();

    const int t4 = tid & 3;
    float4 o[4];
#pragma unroll
    for (int k = 0; k < 4; k++) o[k] = make_float4(0.f, 0.f, 0.f, 0.f);
#pragma unroll 4
    for (int j = 0; j < 32; j++) {
        float p = Ss[r][j];
#pragma unroll
        for (int k = 0; k < 4; k++) {
            float4 v = *(const float4*)&Vs[j][k * 16 + t4 * 4];
            o[k].x += p * v.x; o[k].y += p * v.y; o[k].z += p * v.z; o[k].w += p * v.w;
        }
    }

    const int pos = hmap[s * SEG + r];
    float* Op = g_O + ((long)(b * SEQLEN + pos)) * DIM + h * HEAD_DIM;
#pragma unroll
    for (int k = 0; k < 4; k++)
        *(float4*)(Op + k * 16 + t4 * 4) = tf32x4(o[k]);
}

// ---------------- launch ------------------------------------------------------
extern "C" void kernel_launch(void* const* d_in, const int* in_sizes, int n_in,
                              void* d_out, int out_size)
{
    const float* x      = (const float*)d_in[0];   // [4,4096,1024]
    const float* w_qkv  = (const float*)d_in[1];   // [1024,3072]
    const float* w_proj = (const float*)d_in[2];   // [1024,1024]
    const int*   hmap   = (const int*)  d_in[3];   // [4096]
    float* out = (float*)d_out;                    // [4,4096,1024]

    float* Xc;  cudaGetSymbolAddress((void**)&Xc,  g_Xc);
    float* Q;   cudaGetSymbolAddress((void**)&Q,   g_Q);
    float* KV;  cudaGetSymbolAddress((void**)&KV,  g_KV);
    float* O;   cudaGetSymbolAddress((void**)&O,   g_O);
    float* WqT; cudaGetSymbolAddress((void**)&WqT, g_WqkvT);
    float* WpT; cudaGetSymbolAddress((void**)&WpT, g_WprojT);
    int* qrow;  cudaGetSymbolAddress((void**)&qrow,  g_qrow);
    int* kvrow; cudaGetSymbolAddress((void**)&kvrow, g_kvrow);

    static bool attr_done = false;
    if (!attr_done) {
        cudaFuncSetAttribute(gemm_mma_kernel, cudaFuncAttributeMaxDynamicSharedMemorySize,
                             GSMEM);
        attr_done = true;
    }

    // 1. tables + tf32 pre-rounding
    build_maps_kernel<<<(BATCH * SEQLEN + 255) / 256, 256>>>(hmap);
    convert_x_kernel<<<(BATCH * SEQLEN * DIM / 4) / 256, 256>>>(x);
    transpose_kernel<<<dim3(3 * DIM / 32, DIM / 32), dim3(32, 8)>>>(w_qkv, WqT, DIM, 3 * DIM);
    transpose_kernel<<<dim3(DIM / 32, DIM / 32), dim3(32, 8)>>>(w_proj, WpT, DIM, DIM);

    // 2. Q = x[qrow] @ Wq          (M=16384, N=1024)
    gemm_mma_kernel<<<dim3(1024 / 128, BATCH * SEQLEN / 256), 256, GSMEM>>>(
        Xc, WqT, Q, qrow, 1024);

    // 3. KV = x[kvrow] @ W[k|v]    (M=8192, N=2048)
    gemm_mma_kernel<<<dim3(2048 / 128, BATCH * (SEQLEN / 2) / 256), 256, GSMEM>>>(
        Xc, WqT + (long)DIM * DIM, KV, kvrow, 2048);

    // 4. fused segment attention (+ inverse permutation)
    attn_kernel<<<dim3(NSEG, HEADS, BATCH), 256>>>(hmap);

    // 5. out = O @ w_proj          (M=16384, N=1024)
    gemm_mma_kernel<<<dim3(1024 / 128, BATCH * SEQLEN / 256), 256, GSMEM>>>(
        O, WpT, out, nullptr, 1024);
}

// round 7
// speedup vs baseline: 1.8345x; 1.8345x over previous
#include <cuda_runtime.h>
#include <cuda_fp16.h>
#include <cstdint>
#include <math.h>

#define BATCH    4
#define SEQLEN   4096
#define DIM      1024
#define HEADS    16
#define HEAD_DIM 64
#define SEG      64
#define NSEG     (SEQLEN / SEG)     // 64
#define KSEG     (SEG / 2)          // 32 (dilation 2)
#define KDIM     1024               // GEMM reduction dim
#define SCALE    0.125f             // 64^-0.5

// ---------------- scratch (static device globals; no allocs allowed) --------
__device__ __half g_Xh[BATCH * SEQLEN * DIM];               // fp16 x
__device__ float  g_Q [BATCH * SEQLEN * DIM];               // hilbert-ordered Q (fp32)
__device__ float  g_KV[BATCH * (SEQLEN / 2) * (2 * DIM)];   // dilated K|V (fp32)
__device__ __half g_Oh[BATCH * SEQLEN * DIM];               // attn out, original order (fp16)
__device__ __half g_WqkvT[3 * DIM * DIM];                   // w_qkv^T fp16
__device__ __half g_WprojT[DIM * DIM];                      // w_proj^T fp16
__device__ int    g_qrow [BATCH * SEQLEN];
__device__ int    g_kvrow[BATCH * (SEQLEN / 2)];

// ---------------- helpers -----------------------------------------------------
__device__ __forceinline__ uint32_t smem_u32(const void* p) {
    uint32_t a;
    asm("{ .reg .u64 t; cvta.to.shared.u64 t, %1; cvt.u32.u64 %0, t; }" : "=r"(a) : "l"(p));
    return a;
}
__device__ __forceinline__ void cp_async16(uint32_t dst, const void* src) {
    asm volatile("cp.async.ca.shared.global [%0], [%1], 16;" :: "r"(dst), "l"(src));
}
__device__ __forceinline__ void cp_commit() {
    asm volatile("cp.async.commit_group;" ::: "memory");
}
template <int N>
__device__ __forceinline__ void cp_wait() {
    asm volatile("cp.async.wait_group %0;" :: "n"(N) : "memory");
}

// ---------------- build gather tables ---------------------------------------
__global__ void build_maps_kernel(const int* __restrict__ hmap) {
    int t = blockIdx.x * blockDim.x + threadIdx.x;
    if (t < BATCH * SEQLEN) {
        int b = t / SEQLEN, i = t % SEQLEN;
        g_qrow[t] = b * SEQLEN + hmap[i];
    }
    if (t < BATCH * (SEQLEN / 2)) {
        int b = t / (SEQLEN / 2), m = t % (SEQLEN / 2);
        int s = m / KSEG, j = m % KSEG;
        g_kvrow[t] = b * SEQLEN + hmap[s * SEG + 2 * j];
    }
}

// ---------------- convert x to fp16 ------------------------------------------
__global__ void convert_x_kernel(const float* __restrict__ x) {
    long t = (long)blockIdx.x * blockDim.x + threadIdx.x;
    float4 v = ((const float4*)x)[t];
    __half2* dst = (__half2*)g_Xh + t * 2;
    dst[0] = __floats2half2_rn(v.x, v.y);
    dst[1] = __floats2half2_rn(v.z, v.w);
}

// ---------------- weight transpose + fp16 ------------------------------------
__global__ void transpose_kernel(const float* __restrict__ W, __half* __restrict__ Wt,
                                 int rows, int cols) {  // W[rows][cols] -> Wt[cols][rows]
    __shared__ float t[32][33];
    int bx = blockIdx.x * 32, by = blockIdx.y * 32;
#pragma unroll
    for (int i = 0; i < 32; i += 8) {
        int y = by + threadIdx.y + i, x = bx + threadIdx.x;
        t[threadIdx.y + i][threadIdx.x] = W[(long)y * cols + x];
    }
    __syncthreads();
#pragma unroll
    for (int i = 0; i < 32; i += 8) {
        int y = bx + threadIdx.y + i, x = by + threadIdx.x;
        Wt[(long)y * rows + x] = __float2half_rn(t[threadIdx.x][threadIdx.y + i]);
    }
}

// ---------------- fp16 mma.sync GEMM -------------------------------------------
// C[M,N] = A[rowid[m], :] @ Bt[n, :]^T  (A, Bt fp16; C fp32)
// CTA tile 128x128, 8 warps in 2(M)x4(N), warp tile 64x32.
// K-chunk 32, 3-stage cp.async ring, ldmatrix fragments.
// smem row stride 40 halves (80B) -> ldmatrix conflict-free (slots 0,5,2,7,4,1,6,3).
#define PADH        40
#define STAGE_H     (128 * PADH)              // halves per operand tile
#define STAGE_BYTES (2 * STAGE_H * 2)         // A + B = 20480 B
#define NSTAGE      3
#define GSMEM       (NSTAGE * STAGE_BYTES)    // 61440 B
#define NCHUNK      (KDIM / 32)               // 32

extern __shared__ __align__(16) char dynsmem[];

__global__ __launch_bounds__(256, 2)
void gemm_mma_kernel(const __half* __restrict__ A, const __half* __restrict__ Bt,
                     float* __restrict__ C, const int* __restrict__ rowidx, int ldc)
{
    __shared__ int rowid[128];

    const int tid   = threadIdx.x;
    const int wid   = tid >> 5;       // 0..7
    const int lane  = tid & 31;
    const int warp_m = wid >> 2;      // 0..1 (64 rows each)
    const int warp_n = wid & 3;       // 0..3 (32 cols each)
    const int bm = blockIdx.y * 128;
    const int bn = blockIdx.x * 128;

    if (tid < 128) rowid[tid] = rowidx ? rowidx[bm + tid] : (bm + tid);
    __syncthreads();

    const uint32_t smb = smem_u32(dynsmem);

    auto issue = [&](int chunk) {
        const int s = chunk % NSTAGE;
        const int koff = chunk * 32;                      // halves
        const uint32_t sA = smb + s * STAGE_BYTES;
        const uint32_t sB = sA + STAGE_H * 2;
#pragma unroll
        for (int i = 0; i < 2; i++) {                     // A: 128 rows x 4 granules
            int idx = tid + i * 256;
            int row = idx >> 2, g = idx & 3;
            cp_async16(sA + row * (PADH * 2) + g * 16,
                       A + (long)rowid[row] * KDIM + koff + g * 8);
        }
#pragma unroll
        for (int i = 0; i < 2; i++) {                     // B: 128 rows x 4 granules
            int idx = tid + i * 256;
            int row = idx >> 2, g = idx & 3;
            cp_async16(sB + row * (PADH * 2) + g * 16,
                       Bt + (long)(bn + row) * KDIM + koff + g * 8);
        }
        cp_commit();
    };

    float acc[4][4][4];
#pragma unroll
    for (int i = 0; i < 4; i++)
#pragma unroll
        for (int j = 0; j < 4; j++)
#pragma unroll
            for (int r = 0; r < 4; r++) acc[i][j][r] = 0.0f;

    // per-thread ldmatrix address components
    const int a_quad = lane >> 3;                 // 0..3
    const int a_rin  = lane & 7;
    const int a_rowc = (a_quad & 1) * 8 + a_rin;  // row within 16
    const int a_kofs = (a_quad >> 1) * 8;         // k offset within 16
    const int b_rin  = lane & 7;
    const int b_kofs = ((lane >> 3) & 1) * 8;

    issue(0); issue(1);

    for (int c = 0; c < NCHUNK; ++c) {
        if (c == NCHUNK - 1) cp_wait<0>();
        else                 cp_wait<1>();
        __syncthreads();
        if (c + 2 < NCHUNK) issue(c + 2);

        const uint32_t sA = smb + (c % NSTAGE) * STAGE_BYTES;
        const uint32_t sB = sA + STAGE_H * 2;

#pragma unroll
        for (int ks = 0; ks < 2; ++ks) {
            const int k0 = ks * 16;
            uint32_t af[4][4], bf[4][2];
#pragma unroll
            for (int mt = 0; mt < 4; ++mt) {
                int row = warp_m * 64 + mt * 16 + a_rowc;
                uint32_t addr = sA + (row * PADH + k0 + a_kofs) * 2;
                asm volatile(
                    "ldmatrix.sync.aligned.m8n8.x4.shared.b16 {%0,%1,%2,%3}, [%4];"
                    : "=r"(af[mt][0]), "=r"(af[mt][1]), "=r"(af[mt][2]), "=r"(af[mt][3])
                    : "r"(addr));
            }
#pragma unroll
            for (int nt = 0; nt < 4; ++nt) {
                int row = warp_n * 32 + nt * 8 + b_rin;
                uint32_t addr = sB + (row * PADH + k0 + b_kofs) * 2;
                asm volatile(
                    "ldmatrix.sync.aligned.m8n8.x2.shared.b16 {%0,%1}, [%2];"
                    : "=r"(bf[nt][0]), "=r"(bf[nt][1])
                    : "r"(addr));
            }
#pragma unroll
            for (int mt = 0; mt < 4; ++mt)
#pragma unroll
                for (int nt = 0; nt < 4; ++nt) {
                    asm volatile(
                        "mma.sync.aligned.m16n8k16.row.col.f32.f16.f16.f32 "
                        "{%0,%1,%2,%3}, {%4,%5,%6,%7}, {%8,%9}, {%0,%1,%2,%3};"
                        : "+f"(acc[mt][nt][0]), "+f"(acc[mt][nt][1]),
                          "+f"(acc[mt][nt][2]), "+f"(acc[mt][nt][3])
                        : "r"(af[mt][0]), "r"(af[mt][1]), "r"(af[mt][2]), "r"(af[mt][3]),
                          "r"(bf[nt][0]), "r"(bf[nt][1]));
                }
        }
    }

    // ---- epilogue (fp32 C) ----
    const int gid  = lane >> 2;
    const int tidg = lane & 3;
#pragma unroll
    for (int mt = 0; mt < 4; ++mt) {
        const int row0 = bm + warp_m * 64 + mt * 16 + gid;
#pragma unroll
        for (int nt = 0; nt < 4; ++nt) {
            const int col = bn + warp_n * 32 + nt * 8 + tidg * 2;
            float2 v0 = {acc[mt][nt][0], acc[mt][nt][1]};
            float2 v1 = {acc[mt][nt][2], acc[mt][nt][3]};
            *(float2*)(C + (long)row0 * ldc + col)       = v0;
            *(float2*)(C + (long)(row0 + 8) * ldc + col) = v1;
        }
    }
}

// ---------------- fused segment attention (fp32 compute, fp16 output) --------
__global__ __launch_bounds__(256)
void attn_kernel(const int* __restrict__ hmap)
{
    const int s = blockIdx.x, h = blockIdx.y, b = blockIdx.z;
    __shared__ float Qs[64][68];
    __shared__ float Ks[32][68];
    __shared__ float Vs[32][68];
    __shared__ float Ss[64][33];

    const int tid = threadIdx.x;

    const float* Qbase = g_Q + ((long)(b * SEQLEN + s * SEG)) * DIM + h * HEAD_DIM;
    for (int l = tid; l < 64 * 16; l += 256) {
        int r = l >> 4, g = l & 15;
        *(float4*)&Qs[r][g * 4] = *(const float4*)(Qbase + (long)r * DIM + g * 4);
    }
    const float* Kbase = g_KV + ((long)(b * (SEQLEN / 2) + s * KSEG)) * (2 * DIM) + h * HEAD_DIM;
    const float* Vbase = Kbase + DIM;
    for (int l = tid; l < 32 * 16; l += 256) {
        int r = l >> 4, g = l & 15;
        int gp = g ^ ((r >> 3) & 3);                       // K swizzle
        *(float4*)&Ks[r][gp * 4] = *(const float4*)(Kbase + (long)r * (2 * DIM) + g * 4);
        *(float4*)&Vs[r][g * 4]  = *(const float4*)(Vbase + (long)r * (2 * DIM) + g * 4);
    }
    __syncthreads();

    const int r  = tid >> 2;
    const int cg = (tid & 3) * 8;
    {
        float acc[8] = {0, 0, 0, 0, 0, 0, 0, 0};
#pragma unroll
        for (int gd = 0; gd < 16; ++gd) {
            float4 q = *(const float4*)&Qs[r][gd * 4];
#pragma unroll
            for (int cc = 0; cc < 8; ++cc) {
                const int row = cg + cc;
                float4 kv = *(const float4*)&Ks[row][(gd ^ ((row >> 3) & 3)) * 4];
                acc[cc] += q.x * kv.x + q.y * kv.y + q.z * kv.z + q.w * kv.w;
            }
        }
#pragma unroll
        for (int cc = 0; cc < 8; ++cc) Ss[r][cg + cc] = acc[cc] * SCALE;
    }
    __syncthreads();

    if (tid < 64) {
        float mx = -1e30f;
#pragma unroll
        for (int j = 0; j < 32; j++) mx = fmaxf(mx, Ss[tid][j]);
        float sum = 0.0f;
#pragma unroll
        for (int j = 0; j < 32; j++) {
            float e = __expf(Ss[tid][j] - mx);
            Ss[tid][j] = e;
            sum += e;
        }
        float inv = 1.0f / sum;
#pragma unroll
        for (int j = 0; j < 32; j++) Ss[tid][j] *= inv;
    }
    __syncthreads();

    const int t4 = tid & 3;
    float4 o[4];
#pragma unroll
    for (int k = 0; k < 4; k++) o[k] = make_float4(0.f, 0.f, 0.f, 0.f);
#pragma unroll 4
    for (int j = 0; j < 32; j++) {
        float p = Ss[r][j];
#pragma unroll
        for (int k = 0; k < 4; k++) {
            float4 v = *(const float4*)&Vs[j][k * 16 + t4 * 4];
            o[k].x += p * v.x; o[k].y += p * v.y; o[k].z += p * v.z; o[k].w += p * v.w;
        }
    }

    const int pos = hmap[s * SEG + r];
    __half* Op = g_Oh + ((long)(b * SEQLEN + pos)) * DIM + h * HEAD_DIM;
#pragma unroll
    for (int k = 0; k < 4; k++) {
        __half2 h0 = __floats2half2_rn(o[k].x, o[k].y);
        __half2 h1 = __floats2half2_rn(o[k].z, o[k].w);
        *(__half2*)(Op + k * 16 + t4 * 4)     = h0;
        *(__half2*)(Op + k * 16 + t4 * 4 + 2) = h1;
    }
}

// ---------------- launch ------------------------------------------------------
extern "C" void kernel_launch(void* const* d_in, const int* in_sizes, int n_in,
                              void* d_out, int out_size)
{
    const float* x      = (const float*)d_in[0];   // [4,4096,1024]
    const float* w_qkv  = (const float*)d_in[1];   // [1024,3072]
    const float* w_proj = (const float*)d_in[2];   // [1024,1024]
    const int*   hmap   = (const int*)  d_in[3];   // [4096]
    float* out = (float*)d_out;                    // [4,4096,1024]

    __half* Xh;  cudaGetSymbolAddress((void**)&Xh,  g_Xh);
    float*  Q;   cudaGetSymbolAddress((void**)&Q,   g_Q);
    float*  KV;  cudaGetSymbolAddress((void**)&KV,  g_KV);
    __half* Oh;  cudaGetSymbolAddress((void**)&Oh,  g_Oh);
    __half* WqT; cudaGetSymbolAddress((void**)&WqT, g_WqkvT);
    __half* WpT; cudaGetSymbolAddress((void**)&WpT, g_WprojT);
    int* qrow;  cudaGetSymbolAddress((void**)&qrow,  g_qrow);
    int* kvrow; cudaGetSymbolAddress((void**)&kvrow, g_kvrow);

    static bool attr_done = false;
    if (!attr_done) {
        cudaFuncSetAttribute(gemm_mma_kernel, cudaFuncAttributeMaxDynamicSharedMemorySize,
                             GSMEM);
        attr_done = true;
    }

    // 1. tables + fp16 conversions
    build_maps_kernel<<<(BATCH * SEQLEN + 255) / 256, 256>>>(hmap);
    convert_x_kernel<<<(BATCH * SEQLEN * DIM / 4) / 256, 256>>>(x);
    transpose_kernel<<<dim3(3 * DIM / 32, DIM / 32), dim3(32, 8)>>>(w_qkv, WqT, DIM, 3 * DIM);
    transpose_kernel<<<dim3(DIM / 32, DIM / 32), dim3(32, 8)>>>(w_proj, WpT, DIM, DIM);

    // 2. Q = x[qrow] @ Wq          (M=16384, N=1024)
    gemm_mma_kernel<<<dim3(1024 / 128, BATCH * SEQLEN / 128), 256, GSMEM>>>(
        Xh, WqT, Q, qrow, 1024);

    // 3. KV = x[kvrow] @ W[k|v]    (M=8192, N=2048)
    gemm_mma_kernel<<<dim3(2048 / 128, BATCH * (SEQLEN / 2) / 128), 256, GSMEM>>>(
        Xh, WqT + (long)DIM * DIM, KV, kvrow, 2048);

    // 4. fused segment attention (+ inverse permutation)
    attn_kernel<<<dim3(NSEG, HEADS, BATCH), 256>>>(hmap);

    // 5. out = O @ w_proj          (M=16384, N=1024)
    gemm_mma_kernel<<<dim3(1024 / 128, BATCH * SEQLEN / 128), 256, GSMEM>>>(
        Oh, WpT, out, nullptr, 1024);
}

// round 8
// speedup vs baseline: 1.9697x; 1.0737x over previous
#include <cuda_runtime.h>
#include <cuda_fp16.h>
#include <cstdint>
#include <math.h>

#define BATCH    4
#define SEQLEN   4096
#define DIM      1024
#define HEADS    16
#define HEAD_DIM 64
#define SEG      64
#define NSEG     (SEQLEN / SEG)     // 64
#define KSEG     (SEG / 2)          // 32 (dilation 2)
#define KDIM     1024               // GEMM reduction dim
#define SCALE    0.125f             // 64^-0.5

// ---------------- scratch (static device globals; no allocs allowed) --------
__device__ __half g_Xh [BATCH * SEQLEN * DIM];               // fp16 x
__device__ __half g_Qh [BATCH * SEQLEN * DIM];               // hilbert-ordered Q (fp16)
__device__ __half g_KVh[BATCH * (SEQLEN / 2) * (2 * DIM)];   // dilated K|V (fp16)
__device__ __half g_Oh [BATCH * SEQLEN * DIM];               // attn out, original order
__device__ __half g_WqkvT[3 * DIM * DIM];                    // w_qkv^T fp16
__device__ __half g_WprojT[DIM * DIM];                       // w_proj^T fp16
__device__ int    g_qrow [BATCH * SEQLEN];
__device__ int    g_kvrow[BATCH * (SEQLEN / 2)];

// ---------------- helpers -----------------------------------------------------
__device__ __forceinline__ uint32_t smem_u32(const void* p) {
    uint32_t a;
    asm("{ .reg .u64 t; cvta.to.shared.u64 t, %1; cvt.u32.u64 %0, t; }" : "=r"(a) : "l"(p));
    return a;
}
__device__ __forceinline__ void cp_async16(uint32_t dst, const void* src) {
    asm volatile("cp.async.ca.shared.global [%0], [%1], 16;" :: "r"(dst), "l"(src));
}
__device__ __forceinline__ void cp_commit() {
    asm volatile("cp.async.commit_group;" ::: "memory");
}
template <int N>
__device__ __forceinline__ void cp_wait() {
    asm volatile("cp.async.wait_group %0;" :: "n"(N) : "memory");
}
__device__ __forceinline__ float2 h2f(uint32_t u) {
    __half2 h = *reinterpret_cast<__half2*>(&u);
    return __half22float2(h);
}

// ---------------- build gather tables ---------------------------------------
__global__ void build_maps_kernel(const int* __restrict__ hmap) {
    int t = blockIdx.x * blockDim.x + threadIdx.x;
    if (t < BATCH * SEQLEN) {
        int b = t / SEQLEN, i = t % SEQLEN;
        g_qrow[t] = b * SEQLEN + hmap[i];
    }
    if (t < BATCH * (SEQLEN / 2)) {
        int b = t / (SEQLEN / 2), m = t % (SEQLEN / 2);
        int s = m / KSEG, j = m % KSEG;
        g_kvrow[t] = b * SEQLEN + hmap[s * SEG + 2 * j];
    }
}

// ---------------- convert x to fp16 ------------------------------------------
__global__ void convert_x_kernel(const float* __restrict__ x) {
    long t = (long)blockIdx.x * blockDim.x + threadIdx.x;
    float4 v = ((const float4*)x)[t];
    __half2* dst = (__half2*)g_Xh + t * 2;
    dst[0] = __floats2half2_rn(v.x, v.y);
    dst[1] = __floats2half2_rn(v.z, v.w);
}

// ---------------- weight transpose + fp16 ------------------------------------
__global__ void transpose_kernel(const float* __restrict__ W, __half* __restrict__ Wt,
                                 int rows, int cols) {  // W[rows][cols] -> Wt[cols][rows]
    __shared__ float t[32][33];
    int bx = blockIdx.x * 32, by = blockIdx.y * 32;
#pragma unroll
    for (int i = 0; i < 32; i += 8) {
        int y = by + threadIdx.y + i, x = bx + threadIdx.x;
        t[threadIdx.y + i][threadIdx.x] = W[(long)y * cols + x];
    }
    __syncthreads();
#pragma unroll
    for (int i = 0; i < 32; i += 8) {
        int y = bx + threadIdx.y + i, x = by + threadIdx.x;
        Wt[(long)y * rows + x] = __float2half_rn(t[threadIdx.x][threadIdx.y + i]);
    }
}

// ---------------- fp16 mma.sync GEMM -------------------------------------------
// C[M,N] = A[rowid[m], :] @ Bt[n, :]^T  (A, Bt fp16; C fp32 or fp16)
// CTA tile 128x128, 8 warps in 2(M)x4(N), warp tile 64x32.
// K-chunk 32, 4-stage cp.async ring (wait<2>), ldmatrix fragments.
#define PADH        40
#define STAGE_H     (128 * PADH)              // halves per operand tile
#define STAGE_BYTES (2 * STAGE_H * 2)         // A + B = 20480 B
#define NSTAGE      4
#define GSMEM       (NSTAGE * STAGE_BYTES)    // 81920 B
#define NCHUNK      (KDIM / 32)               // 32

extern __shared__ __align__(16) char dynsmem[];

template <typename OutT>
__global__ __launch_bounds__(256, 2)
void gemm_mma_kernel(const __half* __restrict__ A, const __half* __restrict__ Bt,
                     OutT* __restrict__ C, const int* __restrict__ rowidx, int ldc)
{
    __shared__ int rowid[128];

    const int tid   = threadIdx.x;
    const int wid   = tid >> 5;       // 0..7
    const int lane  = tid & 31;
    const int warp_m = wid >> 2;      // 0..1 (64 rows each)
    const int warp_n = wid & 3;       // 0..3 (32 cols each)
    const int bm = blockIdx.y * 128;
    const int bn = blockIdx.x * 128;

    if (tid < 128) rowid[tid] = rowidx ? rowidx[bm + tid] : (bm + tid);
    __syncthreads();

    const uint32_t smb = smem_u32(dynsmem);

    auto issue = [&](int chunk) {
        const int s = chunk & (NSTAGE - 1);
        const int koff = chunk * 32;                      // halves
        const uint32_t sA = smb + s * STAGE_BYTES;
        const uint32_t sB = sA + STAGE_H * 2;
#pragma unroll
        for (int i = 0; i < 2; i++) {                     // A: 128 rows x 4 granules
            int idx = tid + i * 256;
            int row = idx >> 2, g = idx & 3;
            cp_async16(sA + row * (PADH * 2) + g * 16,
                       A + (long)rowid[row] * KDIM + koff + g * 8);
        }
#pragma unroll
        for (int i = 0; i < 2; i++) {                     // B: 128 rows x 4 granules
            int idx = tid + i * 256;
            int row = idx >> 2, g = idx & 3;
            cp_async16(sB + row * (PADH * 2) + g * 16,
                       Bt + (long)(bn + row) * KDIM + koff + g * 8);
        }
        cp_commit();
    };

    float acc[4][4][4];
#pragma unroll
    for (int i = 0; i < 4; i++)
#pragma unroll
        for (int j = 0; j < 4; j++)
#pragma unroll
            for (int r = 0; r < 4; r++) acc[i][j][r] = 0.0f;

    const int a_quad = lane >> 3;
    const int a_rin  = lane & 7;
    const int a_rowc = (a_quad & 1) * 8 + a_rin;
    const int a_kofs = (a_quad >> 1) * 8;
    const int b_rin  = lane & 7;
    const int b_kofs = ((lane >> 3) & 1) * 8;

    issue(0); issue(1); issue(2);

    for (int c = 0; c < NCHUNK; ++c) {
        cp_wait<2>();                          // chunk c resident
        __syncthreads();                       // visibility + prior readers done
        if (c + 3 < NCHUNK) issue(c + 3);
        else                cp_commit();       // empty group keeps wait<2> exact

        const uint32_t sA = smb + (c & (NSTAGE - 1)) * STAGE_BYTES;
        const uint32_t sB = sA + STAGE_H * 2;

#pragma unroll
        for (int ks = 0; ks < 2; ++ks) {
            const int k0 = ks * 16;
            uint32_t af[4][4], bf[4][2];
#pragma unroll
            for (int mt = 0; mt < 4; ++mt) {
                int row = warp_m * 64 + mt * 16 + a_rowc;
                uint32_t addr = sA + (row * PADH + k0 + a_kofs) * 2;
                asm volatile(
                    "ldmatrix.sync.aligned.m8n8.x4.shared.b16 {%0,%1,%2,%3}, [%4];"
                    : "=r"(af[mt][0]), "=r"(af[mt][1]), "=r"(af[mt][2]), "=r"(af[mt][3])
                    : "r"(addr));
            }
#pragma unroll
            for (int nt = 0; nt < 4; ++nt) {
                int row = warp_n * 32 + nt * 8 + b_rin;
                uint32_t addr = sB + (row * PADH + k0 + b_kofs) * 2;
                asm volatile(
                    "ldmatrix.sync.aligned.m8n8.x2.shared.b16 {%0,%1}, [%2];"
                    : "=r"(bf[nt][0]), "=r"(bf[nt][1])
                    : "r"(addr));
            }
#pragma unroll
            for (int mt = 0; mt < 4; ++mt)
#pragma unroll
                for (int nt = 0; nt < 4; ++nt) {
                    asm volatile(
                        "mma.sync.aligned.m16n8k16.row.col.f32.f16.f16.f32 "
                        "{%0,%1,%2,%3}, {%4,%5,%6,%7}, {%8,%9}, {%0,%1,%2,%3};"
                        : "+f"(acc[mt][nt][0]), "+f"(acc[mt][nt][1]),
                          "+f"(acc[mt][nt][2]), "+f"(acc[mt][nt][3])
                        : "r"(af[mt][0]), "r"(af[mt][1]), "r"(af[mt][2]), "r"(af[mt][3]),
                          "r"(bf[nt][0]), "r"(bf[nt][1]));
                }
        }
    }

    // ---- epilogue ----
    const int gid  = lane >> 2;
    const int tidg = lane & 3;
#pragma unroll
    for (int mt = 0; mt < 4; ++mt) {
        const int row0 = bm + warp_m * 64 + mt * 16 + gid;
#pragma unroll
        for (int nt = 0; nt < 4; ++nt) {
            const int col = bn + warp_n * 32 + nt * 8 + tidg * 2;
            if constexpr (sizeof(OutT) == 2) {
                __half2 v0 = __floats2half2_rn(acc[mt][nt][0], acc[mt][nt][1]);
                __half2 v1 = __floats2half2_rn(acc[mt][nt][2], acc[mt][nt][3]);
                *(__half2*)((__half*)C + (long)row0 * ldc + col)       = v0;
                *(__half2*)((__half*)C + (long)(row0 + 8) * ldc + col) = v1;
            } else {
                float2 v0 = {acc[mt][nt][0], acc[mt][nt][1]};
                float2 v1 = {acc[mt][nt][2], acc[mt][nt][3]};
                *(float2*)((float*)C + (long)row0 * ldc + col)       = v0;
                *(float2*)((float*)C + (long)(row0 + 8) * ldc + col) = v1;
            }
        }
    }
}

// ---------------- fused segment attention (fp16 smem, fp32 accumulate) -------
// Row stride 72 halves (144 B, 16B-aligned). K uses an 8B-granule XOR swizzle:
// granule' = granule ^ ((row>>3)&3), applied at store time (pair-swap for odd keys).
__global__ __launch_bounds__(256)
void attn_kernel(const int* __restrict__ hmap)
{
    const int s = blockIdx.x, h = blockIdx.y, b = blockIdx.z;
    __shared__ __half Qh[64][72];
    __shared__ __half Kh[32][72];
    __shared__ __half Vh[32][72];
    __shared__ float  Ss[64][33];

    const int tid = threadIdx.x;

    const __half* Qbase = g_Qh + ((long)(b * SEQLEN + s * SEG)) * DIM + h * HEAD_DIM;
    for (int l = tid; l < 64 * 8; l += 256) {            // 16B granules (8 halves)
        int r = l >> 3, g = l & 7;
        *(float4*)&Qh[r][g * 8] = *(const float4*)(Qbase + (long)r * DIM + g * 8);
    }
    const __half* Kbase = g_KVh + ((long)(b * (SEQLEN / 2) + s * KSEG)) * (2 * DIM) + h * HEAD_DIM;
    const __half* Vbase = Kbase + DIM;
    for (int l = tid; l < 32 * 8; l += 256) {
        int r = l >> 3, g = l & 7;
        int kk = (r >> 3) & 3;
        uint4 kv = *(const uint4*)(Kbase + (long)r * (2 * DIM) + g * 8);
        int gbase = (2 * g) ^ (kk & 2);                  // 8B-granule pair base after XOR
        if (kk & 1) { uint4 sw = {kv.z, kv.w, kv.x, kv.y}; *(uint4*)&Kh[r][gbase * 4] = sw; }
        else        { *(uint4*)&Kh[r][gbase * 4] = kv; }
        *(float4*)&Vh[r][g * 8] = *(const float4*)(Vbase + (long)r * (2 * DIM) + g * 8);
    }
    __syncthreads();

    // ---- scores: thread -> (q-row r, key-group cg of 8) ----
    const int r  = tid >> 2;
    const int cg = (tid & 3) * 8;
    {
        float acc[8] = {0, 0, 0, 0, 0, 0, 0, 0};
#pragma unroll
        for (int gd = 0; gd < 16; ++gd) {                // 8B granules of 4 halves
            uint2 qu = *(const uint2*)&Qh[r][gd * 4];
            float2 q01 = h2f(qu.x), q23 = h2f(qu.y);
#pragma unroll
            for (int cc = 0; cc < 8; ++cc) {
                const int row = cg + cc;
                const int gp = gd ^ ((row >> 3) & 3);
                uint2 ku = *(const uint2*)&Kh[row][gp * 4];
                float2 k01 = h2f(ku.x), k23 = h2f(ku.y);
                acc[cc] += q01.x * k01.x + q01.y * k01.y + q23.x * k23.x + q23.y * k23.y;
            }
        }
#pragma unroll
        for (int cc = 0; cc < 8; ++cc) Ss[r][cg + cc] = acc[cc] * SCALE;
    }
    __syncthreads();

    if (tid < 64) {
        float mx = -1e30f;
#pragma unroll
        for (int j = 0; j < 32; j++) mx = fmaxf(mx, Ss[tid][j]);
        float sum = 0.0f;
#pragma unroll
        for (int j = 0; j < 32; j++) {
            float e = __expf(Ss[tid][j] - mx);
            Ss[tid][j] = e;
            sum += e;
        }
        float inv = 1.0f / sum;
#pragma unroll
        for (int j = 0; j < 32; j++) Ss[tid][j] *= inv;
    }
    __syncthreads();

    // ---- out = P @ V : thread -> (row r, dims k*16 + t4*4 .. +3) ----
    const int t4 = tid & 3;
    float4 o[4];
#pragma unroll
    for (int k = 0; k < 4; k++) o[k] = make_float4(0.f, 0.f, 0.f, 0.f);
#pragma unroll 4
    for (int j = 0; j < 32; j++) {
        float p = Ss[r][j];
#pragma unroll
        for (int k = 0; k < 4; k++) {
            uint2 vu = *(const uint2*)&Vh[j][(k * 4 + t4) * 4];
            float2 v01 = h2f(vu.x), v23 = h2f(vu.y);
            o[k].x += p * v01.x; o[k].y += p * v01.y;
            o[k].z += p * v23.x; o[k].w += p * v23.y;
        }
    }

    const int pos = hmap[s * SEG + r];
    __half* Op = g_Oh + ((long)(b * SEQLEN + pos)) * DIM + h * HEAD_DIM;
#pragma unroll
    for (int k = 0; k < 4; k++) {
        __half2 h0 = __floats2half2_rn(o[k].x, o[k].y);
        __half2 h1 = __floats2half2_rn(o[k].z, o[k].w);
        uint2 pack = { *(uint32_t*)&h0, *(uint32_t*)&h1 };
        *(uint2*)(Op + k * 16 + t4 * 4) = pack;
    }
}

// ---------------- launch ------------------------------------------------------
extern "C" void kernel_launch(void* const* d_in, const int* in_sizes, int n_in,
                              void* d_out, int out_size)
{
    const float* x      = (const float*)d_in[0];   // [4,4096,1024]
    const float* w_qkv  = (const float*)d_in[1];   // [1024,3072]
    const float* w_proj = (const float*)d_in[2];   // [1024,1024]
    const int*   hmap   = (const int*)  d_in[3];   // [4096]
    float* out = (float*)d_out;                    // [4,4096,1024]

    __half* Xh;  cudaGetSymbolAddress((void**)&Xh,  g_Xh);
    __half* Qh;  cudaGetSymbolAddress((void**)&Qh,  g_Qh);
    __half* KVh; cudaGetSymbolAddress((void**)&KVh, g_KVh);
    __half* Oh;  cudaGetSymbolAddress((void**)&Oh,  g_Oh);
    __half* WqT; cudaGetSymbolAddress((void**)&WqT, g_WqkvT);
    __half* WpT; cudaGetSymbolAddress((void**)&WpT, g_WprojT);
    int* qrow;  cudaGetSymbolAddress((void**)&qrow,  g_qrow);
    int* kvrow; cudaGetSymbolAddress((void**)&kvrow, g_kvrow);

    static bool attr_done = false;
    if (!attr_done) {
        cudaFuncSetAttribute(gemm_mma_kernel<__half>,
                             cudaFuncAttributeMaxDynamicSharedMemorySize, GSMEM);
        cudaFuncSetAttribute(gemm_mma_kernel<float>,
                             cudaFuncAttributeMaxDynamicSharedMemorySize, GSMEM);
        attr_done = true;
    }

    // 1. tables + fp16 conversions
    build_maps_kernel<<<(BATCH * SEQLEN + 255) / 256, 256>>>(hmap);
    convert_x_kernel<<<(BATCH * SEQLEN * DIM / 4) / 256, 256>>>(x);
    transpose_kernel<<<dim3(3 * DIM / 32, DIM / 32), dim3(32, 8)>>>(w_qkv, WqT, DIM, 3 * DIM);
    transpose_kernel<<<dim3(DIM / 32, DIM / 32), dim3(32, 8)>>>(w_proj, WpT, DIM, DIM);

    // 2. Q = x[qrow] @ Wq          (M=16384, N=1024) -> fp16
    gemm_mma_kernel<__half><<<dim3(1024 / 128, BATCH * SEQLEN / 128), 256, GSMEM>>>(
        Xh, WqT, Qh, qrow, 1024);

    // 3. KV = x[kvrow] @ W[k|v]    (M=8192, N=2048) -> fp16
    gemm_mma_kernel<__half><<<dim3(2048 / 128, BATCH * (SEQLEN / 2) / 128), 256, GSMEM>>>(
        Xh, WqT + (long)DIM * DIM, KVh, kvrow, 2048);

    // 4. fused segment attention (+ inverse permutation)
    attn_kernel<<<dim3(NSEG, HEADS, BATCH), 256>>>(hmap);

    // 5. out = O @ w_proj          (M=16384, N=1024) -> fp32
    gemm_mma_kernel<float><<<dim3(1024 / 128, BATCH * SEQLEN / 128), 256, GSMEM>>>(
        Oh, WpT, out, nullptr, 1024);
}

// round 10
// speedup vs baseline: 2.3544x; 1.1953x over previous
#include <cuda_runtime.h>
#include <cuda_fp16.h>
#include <cstdint>
#include <math.h>

#define BATCH    4
#define SEQLEN   4096
#define DIM      1024
#define HEADS    16
#define HEAD_DIM 64
#define SEG      64
#define NSEG     (SEQLEN / SEG)     // 64
#define KSEG     (SEG / 2)          // 32 (dilation 2)
#define KDIM     1024               // GEMM reduction dim
#define SCALE    0.125f             // 64^-0.5

// ---------------- scratch (static device globals; no allocs allowed) --------
__device__ __half g_Xh [BATCH * SEQLEN * DIM];               // fp16 x
__device__ __half g_Qh [BATCH * SEQLEN * DIM];               // hilbert-ordered, pre-scaled Q
__device__ __half g_KVh[BATCH * (SEQLEN / 2) * (2 * DIM)];   // dilated K|V (fp16)
__device__ __half g_Oh [BATCH * SEQLEN * DIM];               // attn out, original order
__device__ __half g_WqkvT[3 * DIM * DIM];                    // w_qkv^T fp16
__device__ __half g_WprojT[DIM * DIM];                       // w_proj^T fp16
__device__ int    g_qrow [BATCH * SEQLEN];
__device__ int    g_kvrow[BATCH * (SEQLEN / 2)];

// ---------------- helpers -----------------------------------------------------
__device__ __forceinline__ uint32_t smem_u32(const void* p) {
    uint32_t a;
    asm("{ .reg .u64 t; cvta.to.shared.u64 t, %1; cvt.u32.u64 %0, t; }" : "=r"(a) : "l"(p));
    return a;
}
__device__ __forceinline__ void cp_async16(uint32_t dst, const void* src) {
    asm volatile("cp.async.ca.shared.global [%0], [%1], 16;" :: "r"(dst), "l"(src));
}
__device__ __forceinline__ void cp_commit() {
    asm volatile("cp.async.commit_group;" ::: "memory");
}
template <int N>
__device__ __forceinline__ void cp_wait() {
    asm volatile("cp.async.wait_group %0;" :: "n"(N) : "memory");
}

// ---------------- build gather tables ---------------------------------------
__global__ void build_maps_kernel(const int* __restrict__ hmap) {
    int t = blockIdx.x * blockDim.x + threadIdx.x;
    if (t < BATCH * SEQLEN) {
        int b = t / SEQLEN, i = t % SEQLEN;
        g_qrow[t] = b * SEQLEN + hmap[i];
    }
    if (t < BATCH * (SEQLEN / 2)) {
        int b = t / (SEQLEN / 2), m = t % (SEQLEN / 2);
        int s = m / KSEG, j = m % KSEG;
        g_kvrow[t] = b * SEQLEN + hmap[s * SEG + 2 * j];
    }
}

// ---------------- convert x to fp16 ------------------------------------------
__global__ void convert_x_kernel(const float* __restrict__ x) {
    long t = (long)blockIdx.x * blockDim.x + threadIdx.x;
    float4 v = ((const float4*)x)[t];
    __half2* dst = (__half2*)g_Xh + t * 2;
    dst[0] = __floats2half2_rn(v.x, v.y);
    dst[1] = __floats2half2_rn(v.z, v.w);
}

// ---------------- weight transpose + fp16 ------------------------------------
__global__ void transpose_kernel(const float* __restrict__ W, __half* __restrict__ Wt,
                                 int rows, int cols) {
    __shared__ float t[32][33];
    int bx = blockIdx.x * 32, by = blockIdx.y * 32;
#pragma unroll
    for (int i = 0; i < 32; i += 8) {
        int y = by + threadIdx.y + i, x = bx + threadIdx.x;
        t[threadIdx.y + i][threadIdx.x] = W[(long)y * cols + x];
    }
    __syncthreads();
#pragma unroll
    for (int i = 0; i < 32; i += 8) {
        int y = bx + threadIdx.y + i, x = by + threadIdx.x;
        Wt[(long)y * rows + x] = __float2half_rn(t[threadIdx.x][threadIdx.y + i]);
    }
}

// ---------------- fp16 mma GEMM body -------------------------------------------
#define PADH        40
#define STAGE_H     (128 * PADH)
#define STAGE_BYTES (2 * STAGE_H * 2)         // 20480 B
#define NSTAGE      4
#define GSMEM       (NSTAGE * STAGE_BYTES)    // 81920 B
#define NCHUNK      (KDIM / 32)               // 32

extern __shared__ __align__(16) char dynsmem[];

template <typename OutT>
__device__ __forceinline__ void gemm_body(const __half* __restrict__ A,
                                          const __half* __restrict__ Bt,
                                          OutT* __restrict__ C,
                                          const int* __restrict__ rowidx,
                                          int ldc, int bx, int by, float alpha)
{
    __shared__ int rowid[128];

    const int tid   = threadIdx.x;
    const int wid   = tid >> 5;
    const int lane  = tid & 31;
    const int warp_m = wid >> 2;
    const int warp_n = wid & 3;
    const int bm = by * 128;
    const int bn = bx * 128;

    if (tid < 128) rowid[tid] = rowidx ? rowidx[bm + tid] : (bm + tid);
    __syncthreads();

    const uint32_t smb = smem_u32(dynsmem);

    auto issue = [&](int chunk) {
        const int s = chunk & (NSTAGE - 1);
        const int koff = chunk * 32;
        const uint32_t sA = smb + s * STAGE_BYTES;
        const uint32_t sB = sA + STAGE_H * 2;
#pragma unroll
        for (int i = 0; i < 2; i++) {
            int idx = tid + i * 256;
            int row = idx >> 2, g = idx & 3;
            cp_async16(sA + row * (PADH * 2) + g * 16,
                       A + (long)rowid[row] * KDIM + koff + g * 8);
        }
#pragma unroll
        for (int i = 0; i < 2; i++) {
            int idx = tid + i * 256;
            int row = idx >> 2, g = idx & 3;
            cp_async16(sB + row * (PADH * 2) + g * 16,
                       Bt + (long)(bn + row) * KDIM + koff + g * 8);
        }
        cp_commit();
    };

    float acc[4][4][4];
#pragma unroll
    for (int i = 0; i < 4; i++)
#pragma unroll
        for (int j = 0; j < 4; j++)
#pragma unroll
            for (int r = 0; r < 4; r++) acc[i][j][r] = 0.0f;

    const int a_quad = lane >> 3;
    const int a_rin  = lane & 7;
    const int a_rowc = (a_quad & 1) * 8 + a_rin;
    const int a_kofs = (a_quad >> 1) * 8;
    const int b_rin  = lane & 7;
    const int b_kofs = ((lane >> 3) & 1) * 8;

    issue(0); issue(1); issue(2);

    for (int c = 0; c < NCHUNK; ++c) {
        cp_wait<2>();
        __syncthreads();
        if (c + 3 < NCHUNK) issue(c + 3);
        else                cp_commit();

        const uint32_t sA = smb + (c & (NSTAGE - 1)) * STAGE_BYTES;
        const uint32_t sB = sA + STAGE_H * 2;

#pragma unroll
        for (int ks = 0; ks < 2; ++ks) {
            const int k0 = ks * 16;
            uint32_t af[4][4], bf[4][2];
#pragma unroll
            for (int mt = 0; mt < 4; ++mt) {
                int row = warp_m * 64 + mt * 16 + a_rowc;
                uint32_t addr = sA + (row * PADH + k0 + a_kofs) * 2;
                asm volatile(
                    "ldmatrix.sync.aligned.m8n8.x4.shared.b16 {%0,%1,%2,%3}, [%4];"
                    : "=r"(af[mt][0]), "=r"(af[mt][1]), "=r"(af[mt][2]), "=r"(af[mt][3])
                    : "r"(addr));
            }
#pragma unroll
            for (int nt = 0; nt < 4; ++nt) {
                int row = warp_n * 32 + nt * 8 + b_rin;
                uint32_t addr = sB + (row * PADH + k0 + b_kofs) * 2;
                asm volatile(
                    "ldmatrix.sync.aligned.m8n8.x2.shared.b16 {%0,%1}, [%2];"
                    : "=r"(bf[nt][0]), "=r"(bf[nt][1])
                    : "r"(addr));
            }
#pragma unroll
            for (int mt = 0; mt < 4; ++mt)
#pragma unroll
                for (int nt = 0; nt < 4; ++nt) {
                    asm volatile(
                        "mma.sync.aligned.m16n8k16.row.col.f32.f16.f16.f32 "
                        "{%0,%1,%2,%3}, {%4,%5,%6,%7}, {%8,%9}, {%0,%1,%2,%3};"
                        : "+f"(acc[mt][nt][0]), "+f"(acc[mt][nt][1]),
                          "+f"(acc[mt][nt][2]), "+f"(acc[mt][nt][3])
                        : "r"(af[mt][0]), "r"(af[mt][1]), "r"(af[mt][2]), "r"(af[mt][3]),
                          "r"(bf[nt][0]), "r"(bf[nt][1]));
                }
        }
    }

    const int gid  = lane >> 2;
    const int tidg = lane & 3;
#pragma unroll
    for (int mt = 0; mt < 4; ++mt) {
        const int row0 = bm + warp_m * 64 + mt * 16 + gid;
#pragma unroll
        for (int nt = 0; nt < 4; ++nt) {
            const int col = bn + warp_n * 32 + nt * 8 + tidg * 2;
            float a0 = acc[mt][nt][0] * alpha, a1 = acc[mt][nt][1] * alpha;
            float a2 = acc[mt][nt][2] * alpha, a3 = acc[mt][nt][3] * alpha;
            if constexpr (sizeof(OutT) == 2) {
                __half2 v0 = __floats2half2_rn(a0, a1);
                __half2 v1 = __floats2half2_rn(a2, a3);
                *(__half2*)((__half*)C + (long)row0 * ldc + col)       = v0;
                *(__half2*)((__half*)C + (long)(row0 + 8) * ldc + col) = v1;
            } else {
                float2 v0 = {a0, a1};
                float2 v1 = {a2, a3};
                *(float2*)((float*)C + (long)row0 * ldc + col)       = v0;
                *(float2*)((float*)C + (long)(row0 + 8) * ldc + col) = v1;
            }
        }
    }
}

// Fused Q + KV GEMM: 2048 CTAs. First 1024 -> Q (8 N-tiles x 128 M-tiles),
// rest -> KV (16 N-tiles x 64 M-tiles).
__global__ __launch_bounds__(256, 2)
void qkv_gemm_kernel(const __half* __restrict__ Xh, const __half* __restrict__ WqT,
                     __half* __restrict__ Qh, __half* __restrict__ KVh,
                     const int* __restrict__ qrow, const int* __restrict__ kvrow)
{
    int id = blockIdx.x;
    if (id < 1024) {
        gemm_body<__half>(Xh, WqT, Qh, qrow, 1024, id & 7, id >> 3, SCALE);
    } else {
        id -= 1024;
        gemm_body<__half>(Xh, WqT + (long)DIM * DIM, KVh, kvrow, 2048, id & 15, id >> 4, 1.0f);
    }
}

__global__ __launch_bounds__(256, 2)
void proj_gemm_kernel(const __half* __restrict__ Oh, const __half* __restrict__ WpT,
                      float* __restrict__ out)
{
    gemm_body<float>(Oh, WpT, out, nullptr, 1024, blockIdx.x, blockIdx.y, 1.0f);
}

// ---------------- tensor-core fused segment attention ------------------------
// 4 warps, warp w owns q-rows w*16..w*16+15 of one (b,h,seg) tile.
// S = Q@K^T via mma (Q pre-scaled by SCALE in GEMM), register softmax,
// P repacked to fp16 A-frags, PV via ldmatrix.x4.trans on V.
#define APAD 72   // half stride; conflict-free for ldmatrix row patterns
__global__ __launch_bounds__(128)
void attn_kernel(const int* __restrict__ hmap)
{
    const int s = blockIdx.x, h = blockIdx.y, b = blockIdx.z;
    __shared__ __half Qs[64][APAD];
    __shared__ __half Ks[32][APAD];
    __shared__ __half Vs[32][APAD];

    const int tid  = threadIdx.x;
    const int wid  = tid >> 5;
    const int lane = tid & 31;
    const int gid  = lane >> 2;
    const int tidg = lane & 3;

    // ---- load tiles (16B granules) ----
    const __half* Qbase = g_Qh + ((long)(b * SEQLEN + s * SEG)) * DIM + h * HEAD_DIM;
    for (int l = tid; l < 64 * 8; l += 128) {
        int r = l >> 3, g = l & 7;
        *(float4*)&Qs[r][g * 8] = *(const float4*)(Qbase + (long)r * DIM + g * 8);
    }
    const __half* Kbase = g_KVh + ((long)(b * (SEQLEN / 2) + s * KSEG)) * (2 * DIM) + h * HEAD_DIM;
    const __half* Vbase = Kbase + DIM;
    for (int l = tid; l < 32 * 8; l += 128) {
        int r = l >> 3, g = l & 7;
        *(float4*)&Ks[r][g * 8] = *(const float4*)(Kbase + (long)r * (2 * DIM) + g * 8);
        *(float4*)&Vs[r][g * 8] = *(const float4*)(Vbase + (long)r * (2 * DIM) + g * 8);
    }
    __syncthreads();

    // ---- S = Q @ K^T : warp computes 16x32 scores ----
    const int a_quad = lane >> 3;
    const int a_rin  = lane & 7;
    const int a_rowc = (a_quad & 1) * 8 + a_rin;
    const int a_kofs = (a_quad >> 1) * 8;
    const int b_rin  = lane & 7;
    const int b_kofs = ((lane >> 3) & 1) * 8;

    float sacc[4][4];
#pragma unroll
    for (int nt = 0; nt < 4; nt++)
#pragma unroll
        for (int r = 0; r < 4; r++) sacc[nt][r] = 0.0f;

#pragma unroll
    for (int ks = 0; ks < 4; ++ks) {
        const int k0 = ks * 16;
        uint32_t af[4], bf[4][2];
        {
            uint32_t addr = smem_u32(&Qs[wid * 16 + a_rowc][k0 + a_kofs]);
            asm volatile(
                "ldmatrix.sync.aligned.m8n8.x4.shared.b16 {%0,%1,%2,%3}, [%4];"
                : "=r"(af[0]), "=r"(af[1]), "=r"(af[2]), "=r"(af[3]) : "r"(addr));
        }
#pragma unroll
        for (int nt = 0; nt < 4; ++nt) {
            uint32_t addr = smem_u32(&Ks[nt * 8 + b_rin][k0 + b_kofs]);
            asm volatile(
                "ldmatrix.sync.aligned.m8n8.x2.shared.b16 {%0,%1}, [%2];"
                : "=r"(bf[nt][0]), "=r"(bf[nt][1]) : "r"(addr));
        }
#pragma unroll
        for (int nt = 0; nt < 4; ++nt)
            asm volatile(
                "mma.sync.aligned.m16n8k16.row.col.f32.f16.f16.f32 "
                "{%0,%1,%2,%3}, {%4,%5,%6,%7}, {%8,%9}, {%0,%1,%2,%3};"
                : "+f"(sacc[nt][0]), "+f"(sacc[nt][1]),
                  "+f"(sacc[nt][2]), "+f"(sacc[nt][3])
                : "r"(af[0]), "r"(af[1]), "r"(af[2]), "r"(af[3]),
                  "r"(bf[nt][0]), "r"(bf[nt][1]));
    }

    // ---- register softmax over 32 keys (rows gid and gid+8) ----
    float mx0 = -1e30f, mx1 = -1e30f;
#pragma unroll
    for (int nt = 0; nt < 4; nt++) {
        mx0 = fmaxf(mx0, fmaxf(sacc[nt][0], sacc[nt][1]));
        mx1 = fmaxf(mx1, fmaxf(sacc[nt][2], sacc[nt][3]));
    }
    mx0 = fmaxf(mx0, __shfl_xor_sync(0xffffffffu, mx0, 1));
    mx0 = fmaxf(mx0, __shfl_xor_sync(0xffffffffu, mx0, 2));
    mx1 = fmaxf(mx1, __shfl_xor_sync(0xffffffffu, mx1, 1));
    mx1 = fmaxf(mx1, __shfl_xor_sync(0xffffffffu, mx1, 2));

    float sum0 = 0.0f, sum1 = 0.0f;
#pragma unroll
    for (int nt = 0; nt < 4; nt++) {
        sacc[nt][0] = __expf(sacc[nt][0] - mx0); sum0 += sacc[nt][0];
        sacc[nt][1] = __expf(sacc[nt][1] - mx0); sum0 += sacc[nt][1];
        sacc[nt][2] = __expf(sacc[nt][2] - mx1); sum1 += sacc[nt][2];
        sacc[nt][3] = __expf(sacc[nt][3] - mx1); sum1 += sacc[nt][3];
    }
    sum0 += __shfl_xor_sync(0xffffffffu, sum0, 1);
    sum0 += __shfl_xor_sync(0xffffffffu, sum0, 2);
    sum1 += __shfl_xor_sync(0xffffffffu, sum1, 1);
    sum1 += __shfl_xor_sync(0xffffffffu, sum1, 2);
    const float inv0 = 1.0f / sum0, inv1 = 1.0f / sum1;

    // ---- pack P to fp16 A-frags: chunk j covers keys 16j..16j+15 ----
    uint32_t pa[2][4];
#pragma unroll
    for (int j = 0; j < 2; j++) {
        __half2 h0 = __floats2half2_rn(sacc[2 * j][0] * inv0, sacc[2 * j][1] * inv0);
        __half2 h1 = __floats2half2_rn(sacc[2 * j][2] * inv1, sacc[2 * j][3] * inv1);
        __half2 h2_ = __floats2half2_rn(sacc[2 * j + 1][0] * inv0, sacc[2 * j + 1][1] * inv0);
        __half2 h3 = __floats2half2_rn(sacc[2 * j + 1][2] * inv1, sacc[2 * j + 1][3] * inv1);
        pa[j][0] = *(uint32_t*)&h0; pa[j][1] = *(uint32_t*)&h1;
        pa[j][2] = *(uint32_t*)&h2_; pa[j][3] = *(uint32_t*)&h3;
    }

    // ---- O = P @ V : 8 dim-tiles, V^T frags via ldmatrix.x4.trans ----
    float oacc[8][4];
#pragma unroll
    for (int nt = 0; nt < 8; nt++)
#pragma unroll
        for (int r = 0; r < 4; r++) oacc[nt][r] = 0.0f;

#pragma unroll
    for (int nt = 0; nt < 8; ++nt) {
        uint32_t vb[4];
        uint32_t addr = smem_u32(&Vs[lane][nt * 8]);   // rows 0..31 = keys
        asm volatile(
            "ldmatrix.sync.aligned.m8n8.x4.trans.shared.b16 {%0,%1,%2,%3}, [%4];"
            : "=r"(vb[0]), "=r"(vb[1]), "=r"(vb[2]), "=r"(vb[3]) : "r"(addr));
#pragma unroll
        for (int j = 0; j < 2; ++j)
            asm volatile(
                "mma.sync.aligned.m16n8k16.row.col.f32.f16.f16.f32 "
                "{%0,%1,%2,%3}, {%4,%5,%6,%7}, {%8,%9}, {%0,%1,%2,%3};"
                : "+f"(oacc[nt][0]), "+f"(oacc[nt][1]),
                  "+f"(oacc[nt][2]), "+f"(oacc[nt][3])
                : "r"(pa[j][0]), "r"(pa[j][1]), "r"(pa[j][2]), "r"(pa[j][3]),
                  "r"(vb[2 * j]), "r"(vb[2 * j + 1]));
    }

    // ---- scatter O rows to original order (fp16) ----
    const int r0 = wid * 16 + gid;
    const int pos0 = hmap[s * SEG + r0];
    const int pos1 = hmap[s * SEG + r0 + 8];
    __half* Op0 = g_Oh + ((long)(b * SEQLEN + pos0)) * DIM + h * HEAD_DIM;
    __half* Op1 = g_Oh + ((long)(b * SEQLEN + pos1)) * DIM + h * HEAD_DIM;
#pragma unroll
    for (int nt = 0; nt < 8; ++nt) {
        __half2 v0 = __floats2half2_rn(oacc[nt][0], oacc[nt][1]);
        __half2 v1 = __floats2half2_rn(oacc[nt][2], oacc[nt][3]);
        *(__half2*)(Op0 + nt * 8 + tidg * 2) = v0;
        *(__half2*)(Op1 + nt * 8 + tidg * 2) = v1;
    }
}

// ---------------- launch ------------------------------------------------------
extern "C" void kernel_launch(void* const* d_in, const int* in_sizes, int n_in,
                              void* d_out, int out_size)
{
    const float* x      = (const float*)d_in[0];
    const float* w_qkv  = (const float*)d_in[1];
    const float* w_proj = (const float*)d_in[2];
    const int*   hmap   = (const int*)  d_in[3];
    float* out = (float*)d_out;

    __half* Xh;  cudaGetSymbolAddress((void**)&Xh,  g_Xh);
    __half* Qh;  cudaGetSymbolAddress((void**)&Qh,  g_Qh);
    __half* KVh; cudaGetSymbolAddress((void**)&KVh, g_KVh);
    __half* Oh;  cudaGetSymbolAddress((void**)&Oh,  g_Oh);
    __half* WqT; cudaGetSymbolAddress((void**)&WqT, g_WqkvT);
    __half* WpT; cudaGetSymbolAddress((void**)&WpT, g_WprojT);
    int* qrow;  cudaGetSymbolAddress((void**)&qrow,  g_qrow);
    int* kvrow; cudaGetSymbolAddress((void**)&kvrow, g_kvrow);

    static bool attr_done = false;
    if (!attr_done) {
        cudaFuncSetAttribute(qkv_gemm_kernel,
                             cudaFuncAttributeMaxDynamicSharedMemorySize, GSMEM);
        cudaFuncSetAttribute(proj_gemm_kernel,
                             cudaFuncAttributeMaxDynamicSharedMemorySize, GSMEM);
        attr_done = true;
    }

    // 1. tables + fp16 conversions
    build_maps_kernel<<<(BATCH * SEQLEN + 255) / 256, 256>>>(hmap);
    convert_x_kernel<<<(BATCH * SEQLEN * DIM / 4) / 256, 256>>>(x);
    transpose_kernel<<<dim3(3 * DIM / 32, DIM / 32), dim3(32, 8)>>>(w_qkv, WqT, DIM, 3 * DIM);
    transpose_kernel<<<dim3(DIM / 32, DIM / 32), dim3(32, 8)>>>(w_proj, WpT, DIM, DIM);

    // 2+3. fused Q (pre-scaled) and KV GEMMs: 1024 + 1024 tiles
    qkv_gemm_kernel<<<2048, 256, GSMEM>>>(Xh, WqT, Qh, KVh, qrow, kvrow);

    // 4. tensor-core fused segment attention (+ inverse permutation)
    attn_kernel<<<dim3(NSEG, HEADS, BATCH), 128>>>(hmap);

    // 5. out = O @ w_proj
    proj_gemm_kernel<<<dim3(1024 / 128, BATCH * SEQLEN / 128), 256, GSMEM>>>(Oh, WpT, out);
}

// round 11
// speedup vs baseline: 2.4171x; 1.0266x over previous
#include <cuda_runtime.h>
#include <cuda_fp16.h>
#include <cstdint>
#include <math.h>

#define BATCH    4
#define SEQLEN   4096
#define DIM      1024
#define HEADS    16
#define HEAD_DIM 64
#define SEG      64
#define NSEG     (SEQLEN / SEG)     // 64
#define KSEG     (SEG / 2)          // 32 (dilation 2)
#define KDIM     1024               // GEMM reduction dim
#define SCALE    0.125f             // 64^-0.5

// ---------------- scratch (static device globals; no allocs allowed) --------
__device__ __half g_Xh [BATCH * SEQLEN * DIM];               // fp16 x
__device__ __half g_Qh [BATCH * SEQLEN * DIM];               // hilbert-ordered, pre-scaled Q
__device__ __half g_KVh[BATCH * (SEQLEN / 2) * (2 * DIM)];   // dilated K|V (fp16)
__device__ __half g_Oh [BATCH * SEQLEN * DIM];               // attn out, original order
__device__ __half g_WqkvT[3 * DIM * DIM];                    // w_qkv^T fp16
__device__ __half g_WprojT[DIM * DIM];                       // w_proj^T fp16
__device__ int    g_qrow [BATCH * SEQLEN];
__device__ int    g_kvrow[BATCH * (SEQLEN / 2)];

// ---------------- helpers -----------------------------------------------------
__device__ __forceinline__ uint32_t smem_u32(const void* p) {
    uint32_t a;
    asm("{ .reg .u64 t; cvta.to.shared.u64 t, %1; cvt.u32.u64 %0, t; }" : "=r"(a) : "l"(p));
    return a;
}
__device__ __forceinline__ void cp_async16(uint32_t dst, const void* src) {
    asm volatile("cp.async.ca.shared.global [%0], [%1], 16;" :: "r"(dst), "l"(src));
}
__device__ __forceinline__ void cp_commit() {
    asm volatile("cp.async.commit_group;" ::: "memory");
}
template <int N>
__device__ __forceinline__ void cp_wait() {
    asm volatile("cp.async.wait_group %0;" :: "n"(N) : "memory");
}

// ---------------- convert x to fp16 (bulk, separate launch) ------------------
__global__ void convert_x_kernel(const float* __restrict__ x) {
    long t = (long)blockIdx.x * blockDim.x + threadIdx.x;
    float4 v = ((const float4*)x)[t];
    __half2* dst = (__half2*)g_Xh + t * 2;
    dst[0] = __floats2half2_rn(v.x, v.y);
    dst[1] = __floats2half2_rn(v.z, v.w);
}

// ---------------- fused prep: both transposes + gather maps ------------------
// blocks [0, 3072)        : w_qkv^T  (bx = id % 96, by = id / 96)
// blocks [3072, 4096)     : w_proj^T (bx = id % 32, by = id / 32)
// blocks [4096, 4160)     : gather maps
__device__ __forceinline__ void transpose_body(const float* __restrict__ W,
                                               __half* __restrict__ Wt,
                                               int rows, int cols, int bxi, int byi,
                                               int tx, int ty)
{
    __shared__ float t[32][33];
    int bx = bxi * 32, by = byi * 32;
#pragma unroll
    for (int i = 0; i < 32; i += 8) {
        int y = by + ty + i, x = bx + tx;
        t[ty + i][tx] = W[(long)y * cols + x];
    }
    __syncthreads();
#pragma unroll
    for (int i = 0; i < 32; i += 8) {
        int y = bx + ty + i, x = by + tx;
        Wt[(long)y * rows + x] = __float2half_rn(t[tx][ty + i]);
    }
}

__global__ __launch_bounds__(256)
void prep_kernel(const float* __restrict__ w_qkv, const float* __restrict__ w_proj,
                 const int* __restrict__ hmap)
{
    const int id = blockIdx.x;
    const int tx = threadIdx.x & 31, ty = threadIdx.x >> 5;
    if (id < 3072) {
        transpose_body(w_qkv, g_WqkvT, DIM, 3 * DIM, id % 96, id / 96, tx, ty);
    } else if (id < 4096) {
        int i2 = id - 3072;
        transpose_body(w_proj, g_WprojT, DIM, DIM, i2 % 32, i2 / 32, tx, ty);
    } else {
        int t = (id - 4096) * 256 + threadIdx.x;
        if (t < BATCH * SEQLEN) {
            int b = t / SEQLEN, i = t % SEQLEN;
            g_qrow[t] = b * SEQLEN + hmap[i];
        }
        if (t < BATCH * (SEQLEN / 2)) {
            int b = t / (SEQLEN / 2), m = t % (SEQLEN / 2);
            int s = m / KSEG, j = m % KSEG;
            g_kvrow[t] = b * SEQLEN + hmap[s * SEG + 2 * j];
        }
    }
}

// ---------------- fp16 mma GEMM body -------------------------------------------
#define PADH        40
#define STAGE_H     (128 * PADH)
#define STAGE_BYTES (2 * STAGE_H * 2)         // 20480 B
#define NSTAGE      4
#define GSMEM       (NSTAGE * STAGE_BYTES)    // 81920 B
#define NCHUNK      (KDIM / 32)               // 32

extern __shared__ __align__(16) char dynsmem[];

template <typename OutT>
__device__ __forceinline__ void gemm_body(const __half* __restrict__ A,
                                          const __half* __restrict__ Bt,
                                          OutT* __restrict__ C,
                                          const int* __restrict__ rowidx,
                                          int ldc, int bx, int by, float alpha)
{
    __shared__ int rowid[128];

    const int tid   = threadIdx.x;
    const int wid   = tid >> 5;
    const int lane  = tid & 31;
    const int warp_m = wid >> 2;
    const int warp_n = wid & 3;
    const int bm = by * 128;
    const int bn = bx * 128;

    if (tid < 128) rowid[tid] = rowidx ? rowidx[bm + tid] : (bm + tid);
    __syncthreads();

    const uint32_t smb = smem_u32(dynsmem);

    auto issue = [&](int chunk) {
        const int s = chunk & (NSTAGE - 1);
        const int koff = chunk * 32;
        const uint32_t sA = smb + s * STAGE_BYTES;
        const uint32_t sB = sA + STAGE_H * 2;
#pragma unroll
        for (int i = 0; i < 2; i++) {
            int idx = tid + i * 256;
            int row = idx >> 2, g = idx & 3;
            cp_async16(sA + row * (PADH * 2) + g * 16,
                       A + (long)rowid[row] * KDIM + koff + g * 8);
        }
#pragma unroll
        for (int i = 0; i < 2; i++) {
            int idx = tid + i * 256;
            int row = idx >> 2, g = idx & 3;
            cp_async16(sB + row * (PADH * 2) + g * 16,
                       Bt + (long)(bn + row) * KDIM + koff + g * 8);
        }
        cp_commit();
    };

    float acc[4][4][4];
#pragma unroll
    for (int i = 0; i < 4; i++)
#pragma unroll
        for (int j = 0; j < 4; j++)
#pragma unroll
            for (int r = 0; r < 4; r++) acc[i][j][r] = 0.0f;

    const int a_quad = lane >> 3;
    const int a_rin  = lane & 7;
    const int a_rowc = (a_quad & 1) * 8 + a_rin;
    const int a_kofs = (a_quad >> 1) * 8;
    // B x4 ldmatrix: matrix m = lane>>3 -> row pair (m>>1), k-half (m&1)
    const int b_rowc = ((lane >> 4) & 1) * 8 + (lane & 7);
    const int b_kofs = ((lane >> 3) & 1) * 8;

    issue(0); issue(1); issue(2);

    for (int c = 0; c < NCHUNK; ++c) {
        cp_wait<2>();
        __syncthreads();
        if (c + 3 < NCHUNK) issue(c + 3);
        else                cp_commit();

        const uint32_t sA = smb + (c & (NSTAGE - 1)) * STAGE_BYTES;
        const uint32_t sB = sA + STAGE_H * 2;

#pragma unroll
        for (int ks = 0; ks < 2; ++ks) {
            const int k0 = ks * 16;
            uint32_t af[4][4], bf[4][2];
#pragma unroll
            for (int mt = 0; mt < 4; ++mt) {
                int row = warp_m * 64 + mt * 16 + a_rowc;
                uint32_t addr = sA + (row * PADH + k0 + a_kofs) * 2;
                asm volatile(
                    "ldmatrix.sync.aligned.m8n8.x4.shared.b16 {%0,%1,%2,%3}, [%4];"
                    : "=r"(af[mt][0]), "=r"(af[mt][1]), "=r"(af[mt][2]), "=r"(af[mt][3])
                    : "r"(addr));
            }
#pragma unroll
            for (int np = 0; np < 2; ++np) {              // nt pair: covers nt=2np, 2np+1
                int row = warp_n * 32 + np * 16 + b_rowc;
                uint32_t addr = sB + (row * PADH + k0 + b_kofs) * 2;
                asm volatile(
                    "ldmatrix.sync.aligned.m8n8.x4.shared.b16 {%0,%1,%2,%3}, [%4];"
                    : "=r"(bf[2 * np][0]), "=r"(bf[2 * np][1]),
                      "=r"(bf[2 * np + 1][0]), "=r"(bf[2 * np + 1][1])
                    : "r"(addr));
            }
#pragma unroll
            for (int mt = 0; mt < 4; ++mt)
#pragma unroll
                for (int nt = 0; nt < 4; ++nt) {
                    asm volatile(
                        "mma.sync.aligned.m16n8k16.row.col.f32.f16.f16.f32 "
                        "{%0,%1,%2,%3}, {%4,%5,%6,%7}, {%8,%9}, {%0,%1,%2,%3};"
                        : "+f"(acc[mt][nt][0]), "+f"(acc[mt][nt][1]),
                          "+f"(acc[mt][nt][2]), "+f"(acc[mt][nt][3])
                        : "r"(af[mt][0]), "r"(af[mt][1]), "r"(af[mt][2]), "r"(af[mt][3]),
                          "r"(bf[nt][0]), "r"(bf[nt][1]));
                }
        }
    }

    const int gid  = lane >> 2;
    const int tidg = lane & 3;
#pragma unroll
    for (int mt = 0; mt < 4; ++mt) {
        const int row0 = bm + warp_m * 64 + mt * 16 + gid;
#pragma unroll
        for (int nt = 0; nt < 4; ++nt) {
            const int col = bn + warp_n * 32 + nt * 8 + tidg * 2;
            float a0 = acc[mt][nt][0] * alpha, a1 = acc[mt][nt][1] * alpha;
            float a2 = acc[mt][nt][2] * alpha, a3 = acc[mt][nt][3] * alpha;
            if constexpr (sizeof(OutT) == 2) {
                __half2 v0 = __floats2half2_rn(a0, a1);
                __half2 v1 = __floats2half2_rn(a2, a3);
                *(__half2*)((__half*)C + (long)row0 * ldc + col)       = v0;
                *(__half2*)((__half*)C + (long)(row0 + 8) * ldc + col) = v1;
            } else {
                float2 v0 = {a0, a1};
                float2 v1 = {a2, a3};
                *(float2*)((float*)C + (long)row0 * ldc + col)       = v0;
                *(float2*)((float*)C + (long)(row0 + 8) * ldc + col) = v1;
            }
        }
    }
}

// Fused Q + KV GEMM: 2048 CTAs. First 1024 -> Q (8 N-tiles x 128 M-tiles),
// rest -> KV (16 N-tiles x 64 M-tiles).
__global__ __launch_bounds__(256, 2)
void qkv_gemm_kernel(const __half* __restrict__ Xh, const __half* __restrict__ WqT,
                     __half* __restrict__ Qh, __half* __restrict__ KVh,
                     const int* __restrict__ qrow, const int* __restrict__ kvrow)
{
    int id = blockIdx.x;
    if (id < 1024) {
        gemm_body<__half>(Xh, WqT, Qh, qrow, 1024, id & 7, id >> 3, SCALE);
    } else {
        id -= 1024;
        gemm_body<__half>(Xh, WqT + (long)DIM * DIM, KVh, kvrow, 2048, id & 15, id >> 4, 1.0f);
    }
}

__global__ __launch_bounds__(256, 2)
void proj_gemm_kernel(const __half* __restrict__ Oh, const __half* __restrict__ WpT,
                      float* __restrict__ out)
{
    gemm_body<float>(Oh, WpT, out, nullptr, 1024, blockIdx.x, blockIdx.y, 1.0f);
}

// ---------------- tensor-core fused segment attention ------------------------
#define APAD 72
__global__ __launch_bounds__(128)
void attn_kernel(const int* __restrict__ hmap)
{
    const int s = blockIdx.x, h = blockIdx.y, b = blockIdx.z;
    __shared__ __half Qs[64][APAD];
    __shared__ __half Ks[32][APAD];
    __shared__ __half Vs[32][APAD];

    const int tid  = threadIdx.x;
    const int wid  = tid >> 5;
    const int lane = tid & 31;
    const int gid  = lane >> 2;
    const int tidg = lane & 3;

    const __half* Qbase = g_Qh + ((long)(b * SEQLEN + s * SEG)) * DIM + h * HEAD_DIM;
    for (int l = tid; l < 64 * 8; l += 128) {
        int r = l >> 3, g = l & 7;
        *(float4*)&Qs[r][g * 8] = *(const float4*)(Qbase + (long)r * DIM + g * 8);
    }
    const __half* Kbase = g_KVh + ((long)(b * (SEQLEN / 2) + s * KSEG)) * (2 * DIM) + h * HEAD_DIM;
    const __half* Vbase = Kbase + DIM;
    for (int l = tid; l < 32 * 8; l += 128) {
        int r = l >> 3, g = l & 7;
        *(float4*)&Ks[r][g * 8] = *(const float4*)(Kbase + (long)r * (2 * DIM) + g * 8);
        *(float4*)&Vs[r][g * 8] = *(const float4*)(Vbase + (long)r * (2 * DIM) + g * 8);
    }
    __syncthreads();

    const int a_quad = lane >> 3;
    const int a_rin  = lane & 7;
    const int a_rowc = (a_quad & 1) * 8 + a_rin;
    const int a_kofs = (a_quad >> 1) * 8;
    const int b_rin  = lane & 7;
    const int b_kofs = ((lane >> 3) & 1) * 8;

    float sacc[4][4];
#pragma unroll
    for (int nt = 0; nt < 4; nt++)
#pragma unroll
        for (int r = 0; r < 4; r++) sacc[nt][r] = 0.0f;

#pragma unroll
    for (int ks = 0; ks < 4; ++ks) {
        const int k0 = ks * 16;
        uint32_t af[4], bf[4][2];
        {
            uint32_t addr = smem_u32(&Qs[wid * 16 + a_rowc][k0 + a_kofs]);
            asm volatile(
                "ldmatrix.sync.aligned.m8n8.x4.shared.b16 {%0,%1,%2,%3}, [%4];"
                : "=r"(af[0]), "=r"(af[1]), "=r"(af[2]), "=r"(af[3]) : "r"(addr));
        }
#pragma unroll
        for (int nt = 0; nt < 4; ++nt) {
            uint32_t addr = smem_u32(&Ks[nt * 8 + b_rin][k0 + b_kofs]);
            asm volatile(
                "ldmatrix.sync.aligned.m8n8.x2.shared.b16 {%0,%1}, [%2];"
                : "=r"(bf[nt][0]), "=r"(bf[nt][1]) : "r"(addr));
        }
#pragma unroll
        for (int nt = 0; nt < 4; ++nt)
            asm volatile(
                "mma.sync.aligned.m16n8k16.row.col.f32.f16.f16.f32 "
                "{%0,%1,%2,%3}, {%4,%5,%6,%7}, {%8,%9}, {%0,%1,%2,%3};"
                : "+f"(sacc[nt][0]), "+f"(sacc[nt][1]),
                  "+f"(sacc[nt][2]), "+f"(sacc[nt][3])
                : "r"(af[0]), "r"(af[1]), "r"(af[2]), "r"(af[3]),
                  "r"(bf[nt][0]), "r"(bf[nt][1]));
    }

    float mx0 = -1e30f, mx1 = -1e30f;
#pragma unroll
    for (int nt = 0; nt < 4; nt++) {
        mx0 = fmaxf(mx0, fmaxf(sacc[nt][0], sacc[nt][1]));
        mx1 = fmaxf(mx1, fmaxf(sacc[nt][2], sacc[nt][3]));
    }
    mx0 = fmaxf(mx0, __shfl_xor_sync(0xffffffffu, mx0, 1));
    mx0 = fmaxf(mx0, __shfl_xor_sync(0xffffffffu, mx0, 2));
    mx1 = fmaxf(mx1, __shfl_xor_sync(0xffffffffu, mx1, 1));
    mx1 = fmaxf(mx1, __shfl_xor_sync(0xffffffffu, mx1, 2));

    float sum0 = 0.0f, sum1 = 0.0f;
#pragma unroll
    for (int nt = 0; nt < 4; nt++) {
        sacc[nt][0] = __expf(sacc[nt][0] - mx0); sum0 += sacc[nt][0];
        sacc[nt][1] = __expf(sacc[nt][1] - mx0); sum0 += sacc[nt][1];
        sacc[nt][2] = __expf(sacc[nt][2] - mx1); sum1 += sacc[nt][2];
        sacc[nt][3] = __expf(sacc[nt][3] - mx1); sum1 += sacc[nt][3];
    }
    sum0 += __shfl_xor_sync(0xffffffffu, sum0, 1);
    sum0 += __shfl_xor_sync(0xffffffffu, sum0, 2);
    sum1 += __shfl_xor_sync(0xffffffffu, sum1, 1);
    sum1 += __shfl_xor_sync(0xffffffffu, sum1, 2);
    const float inv0 = 1.0f / sum0, inv1 = 1.0f / sum1;

    uint32_t pa[2][4];
#pragma unroll
    for (int j = 0; j < 2; j++) {
        __half2 h0 = __floats2half2_rn(sacc[2 * j][0] * inv0, sacc[2 * j][1] * inv0);
        __half2 h1 = __floats2half2_rn(sacc[2 * j][2] * inv1, sacc[2 * j][3] * inv1);
        __half2 h2_ = __floats2half2_rn(sacc[2 * j + 1][0] * inv0, sacc[2 * j + 1][1] * inv0);
        __half2 h3 = __floats2half2_rn(sacc[2 * j + 1][2] * inv1, sacc[2 * j + 1][3] * inv1);
        pa[j][0] = *(uint32_t*)&h0; pa[j][1] = *(uint32_t*)&h1;
        pa[j][2] = *(uint32_t*)&h2_; pa[j][3] = *(uint32_t*)&h3;
    }

    float oacc[8][4];
#pragma unroll
    for (int nt = 0; nt < 8; nt++)
#pragma unroll
        for (int r = 0; r < 4; r++) oacc[nt][r] = 0.0f;

#pragma unroll
    for (int nt = 0; nt < 8; ++nt) {
        uint32_t vb[4];
        uint32_t addr = smem_u32(&Vs[lane][nt * 8]);
        asm volatile(
            "ldmatrix.sync.aligned.m8n8.x4.trans.shared.b16 {%0,%1,%2,%3}, [%4];"
            : "=r"(vb[0]), "=r"(vb[1]), "=r"(vb[2]), "=r"(vb[3]) : "r"(addr));
#pragma unroll
        for (int j = 0; j < 2; ++j)
            asm volatile(
                "mma.sync.aligned.m16n8k16.row.col.f32.f16.f16.f32 "
                "{%0,%1,%2,%3}, {%4,%5,%6,%7}, {%8,%9}, {%0,%1,%2,%3};"
                : "+f"(oacc[nt][0]), "+f"(oacc[nt][1]),
                  "+f"(oacc[nt][2]), "+f"(oacc[nt][3])
                : "r"(pa[j][0]), "r"(pa[j][1]), "r"(pa[j][2]), "r"(pa[j][3]),
                  "r"(vb[2 * j]), "r"(vb[2 * j + 1]));
    }

    const int r0 = wid * 16 + gid;
    const int pos0 = hmap[s * SEG + r0];
    const int pos1 = hmap[s * SEG + r0 + 8];
    __half* Op0 = g_Oh + ((long)(b * SEQLEN + pos0)) * DIM + h * HEAD_DIM;
    __half* Op1 = g_Oh + ((long)(b * SEQLEN + pos1)) * DIM + h * HEAD_DIM;
#pragma unroll
    for (int nt = 0; nt < 8; ++nt) {
        __half2 v0 = __floats2half2_rn(oacc[nt][0], oacc[nt][1]);
        __half2 v1 = __floats2half2_rn(oacc[nt][2], oacc[nt][3]);
        *(__half2*)(Op0 + nt * 8 + tidg * 2) = v0;
        *(__half2*)(Op1 + nt * 8 + tidg * 2) = v1;
    }
}

// ---------------- launch ------------------------------------------------------
extern "C" void kernel_launch(void* const* d_in, const int* in_sizes, int n_in,
                              void* d_out, int out_size)
{
    const float* x      = (const float*)d_in[0];
    const float* w_qkv  = (const float*)d_in[1];
    const float* w_proj = (const float*)d_in[2];
    const int*   hmap   = (const int*)  d_in[3];
    float* out = (float*)d_out;

    __half* Xh;  cudaGetSymbolAddress((void**)&Xh,  g_Xh);
    __half* Qh;  cudaGetSymbolAddress((void**)&Qh,  g_Qh);
    __half* KVh; cudaGetSymbolAddress((void**)&KVh, g_KVh);
    __half* Oh;  cudaGetSymbolAddress((void**)&Oh,  g_Oh);
    __half* WqT; cudaGetSymbolAddress((void**)&WqT, g_WqkvT);
    __half* WpT; cudaGetSymbolAddress((void**)&WpT, g_WprojT);
    int* qrow;  cudaGetSymbolAddress((void**)&qrow,  g_qrow);
    int* kvrow; cudaGetSymbolAddress((void**)&kvrow, g_kvrow);

    static bool attr_done = false;
    if (!attr_done) {
        cudaFuncSetAttribute(qkv_gemm_kernel,
                             cudaFuncAttributeMaxDynamicSharedMemorySize, GSMEM);
        cudaFuncSetAttribute(proj_gemm_kernel,
                             cudaFuncAttributeMaxDynamicSharedMemorySize, GSMEM);
        attr_done = true;
    }

    // 1. fp16 convert + fused prep (transposes + maps)
    convert_x_kernel<<<(BATCH * SEQLEN * DIM / 4) / 256, 256>>>(x);
    prep_kernel<<<4160, 256>>>(w_qkv, w_proj, hmap);

    // 2+3. fused Q (pre-scaled) and KV GEMMs: 1024 + 1024 tiles
    qkv_gemm_kernel<<<2048, 256, GSMEM>>>(Xh, WqT, Qh, KVh, qrow, kvrow);

    // 4. tensor-core fused segment attention (+ inverse permutation)
    attn_kernel<<<dim3(NSEG, HEADS, BATCH), 128>>>(hmap);

    // 5. out = O @ w_proj
    proj_gemm_kernel<<<dim3(1024 / 128, BATCH * SEQLEN / 128), 256, GSMEM>>>(Oh, WpT, out);
}